// round 5
// baseline (speedup 1.0000x reference)
#include <cuda_runtime.h>
#include <cstdint>

#define N_DIM   512
#define K_DIM   32768
#define L_DIM   64
#define KTILE   128
#define NCHUNK  32
#define NCHUNKS (N_DIM / NCHUNK)     // 16
#define TOUT    1048608

#define CS_PITCH   136               // floats; 544B rows (16B-mult), conflict-free frags
#define STAGE_FL   (NCHUNK * CS_PITCH)      // 4352 floats = 17408 B
#define NSTAGE     3
#define SMEM_BYTES (NSTAGE * STAGE_FL * 4)  // 52224 B (>= 33792 epilogue reuse)
#define FR_PITCH   66

// V pre-formatted as tf32 B-fragments: [cc(16)][s(4)][bt(8)][lane(32)] float2
__device__ float2 g_vf[16 * 4 * 8 * 32];

static __device__ __forceinline__ uint32_t f2tf32(float f) {
    uint32_t u;
    asm("cvt.rna.tf32.f32 %0, %1;" : "=r"(u) : "f"(f));
    return u;
}
static __device__ __forceinline__ uint32_t smem_u32(const void* p) {
    uint32_t a;
    asm("{ .reg .u64 t; cvta.to.shared.u64 t, %1; cvt.u32.u64 %0, t; }" : "=r"(a) : "l"(p));
    return a;
}
static __device__ __forceinline__ void cp_async16(uint32_t dst, const void* src) {
    asm volatile("cp.async.cg.shared.global [%0], [%1], 16;" :: "r"(dst), "l"(src));
}
static __device__ __forceinline__ void cp_commit() {
    asm volatile("cp.async.commit_group;" ::: "memory");
}
template <int N> static __device__ __forceinline__ void cp_wait() {
    asm volatile("cp.async.wait_group %0;" :: "n"(N) : "memory");
}
static __device__ __forceinline__ void mma_tf32(float d[4], const uint32_t a[4],
                                                const uint32_t b[2]) {
    asm volatile(
        "mma.sync.aligned.m16n8k8.row.col.f32.tf32.tf32.f32 "
        "{%0,%1,%2,%3}, {%4,%5,%6,%7}, {%8,%9}, {%0,%1,%2,%3};"
        : "+f"(d[0]), "+f"(d[1]), "+f"(d[2]), "+f"(d[3])
        : "r"(a[0]), "r"(a[1]), "r"(a[2]), "r"(a[3]), "r"(b[0]), "r"(b[1]));
}

// ---- fused prep: V -> tf32 B-fragments, zero boundary tiles ----
__global__ void prep_kernel(const float* __restrict__ V, float* __restrict__ y) {
    const int idx = blockIdx.x * blockDim.x + threadIdx.x;
    if (idx < 16384) {
        const int lane = idx & 31;
        const int bt   = (idx >> 5) & 7;
        const int s    = (idx >> 8) & 3;
        const int cc   = idx >> 10;
        const int grp  = lane >> 2, qid = lane & 3;
        const int l = bt * 8 + grp;
        const int n = cc * NCHUNK + s * 8 + qid;
        float2 v;
        v.x = __uint_as_float(f2tf32(V[l * N_DIM + n]));
        v.y = __uint_as_float(f2tf32(V[l * N_DIM + n + 4]));
        g_vf[idx] = v;
    } else {
        const int i = idx - 16384;
        if (i < 8 * 257 * 32) {
            const int b = i / (257 * 32);
            const int r = i % (257 * 32);
            const int t = r >> 5, j = r & 31;
            y[(size_t)b * TOUT + (size_t)t * 4096 + j] = 0.f;
        }
    }
}

// ---- main: CTA = (b, 128 frames), 4 warps, warp tile m32 x n64, cp.async x3 ----
__global__ void __launch_bounds__(128)
decoder_kernel(const float* __restrict__ c, float* __restrict__ y) {
    extern __shared__ __align__(16) float sm[];

    const int tid  = threadIdx.x;
    const int wid  = tid >> 5;
    const int lane = tid & 31;
    const int grp  = lane >> 2;
    const int qid  = lane & 3;
    const int k0   = blockIdx.x * KTILE;
    const int b    = blockIdx.y;
    const int wm   = wid * 32;

    const float* cb = c + ((size_t)b * N_DIM) * K_DIM + k0;
    const uint32_t sbase = smem_u32(sm);

    // per-thread cp.async mapping: 8 x 16B per stage (n = idx>>5, q = idx&31)
    const int ld_n = tid >> 5;          // base n within the 4-row group per iter
    const int ld_q = tid & 31;

    float acc[2][8][4];
    #pragma unroll
    for (int mt = 0; mt < 2; ++mt)
        #pragma unroll
        for (int bt = 0; bt < 8; ++bt)
            #pragma unroll
            for (int r = 0; r < 4; ++r) acc[mt][bt][r] = 0.f;

    // prologue: stages 0,1
    #pragma unroll
    for (int st = 0; st < 2; ++st) {
        const uint32_t dbase = sbase + st * (STAGE_FL * 4);
        #pragma unroll
        for (int it = 0; it < 8; ++it) {
            const int n = it * 4 + ld_n;
            cp_async16(dbase + n * (CS_PITCH * 4) + ld_q * 16,
                       cb + (size_t)(st * NCHUNK + n) * K_DIM + 4 * ld_q);
        }
        cp_commit();
    }

    #pragma unroll 1
    for (int cc = 0; cc < NCHUNKS; ++cc) {
        if (cc == NCHUNKS - 1) cp_wait<0>(); else cp_wait<1>();
        __syncthreads();

        // issue stage cc+2 (its buffer was consumed at chunk cc-1, all warps past sync)
        if (cc + 2 < NCHUNKS) {
            const uint32_t dbase = sbase + ((cc + 2) % NSTAGE) * (STAGE_FL * 4);
            const size_t gn0 = (size_t)(cc + 2) * NCHUNK;
            #pragma unroll
            for (int it = 0; it < 8; ++it) {
                const int n = it * 4 + ld_n;
                cp_async16(dbase + n * (CS_PITCH * 4) + ld_q * 16,
                           cb + (gn0 + n) * K_DIM + 4 * ld_q);
            }
            cp_commit();
        }

        // compute on stage cc%3 (raw fp32 in SMEM; cvt at fragment load)
        const float* cs = sm + (cc % NSTAGE) * STAGE_FL;
        #pragma unroll
        for (int s = 0; s < 4; ++s) {
            const float2* vf = g_vf + ((size_t)(cc * 4 + s) * 8) * 32 + lane;
            uint32_t bf[8][2];
            #pragma unroll
            for (int bt = 0; bt < 8; ++bt) {
                float2 bv = __ldg(vf + bt * 32);
                bf[bt][0] = __float_as_uint(bv.x);
                bf[bt][1] = __float_as_uint(bv.y);
            }
            const float* ar0 = cs + (8 * s + qid) * CS_PITCH + wm + grp;
            const float* ar1 = cs + (8 * s + qid + 4) * CS_PITCH + wm + grp;
            uint32_t a[2][4];
            #pragma unroll
            for (int mt = 0; mt < 2; ++mt) {
                a[mt][0] = f2tf32(ar0[mt * 16]);
                a[mt][1] = f2tf32(ar0[mt * 16 + 8]);
                a[mt][2] = f2tf32(ar1[mt * 16]);
                a[mt][3] = f2tf32(ar1[mt * 16 + 8]);
            }
            #pragma unroll
            for (int mt = 0; mt < 2; ++mt)
                #pragma unroll
                for (int bt = 0; bt < 8; ++bt)
                    mma_tf32(acc[mt][bt], a[mt], bf[bt]);
        }
    }
    __syncthreads();   // all warps done reading stage buffers before epilogue reuse

    // ---- epilogue: stage frames (128 x FR_PITCH), overlap-add ----
    float* fr = sm;
    #pragma unroll
    for (int mt = 0; mt < 2; ++mt) {
        #pragma unroll
        for (int bt = 0; bt < 8; ++bt) {
            const int row = wm + mt * 16 + grp;
            const int col = bt * 8 + 2 * qid;
            *reinterpret_cast<float2*>(fr + row * FR_PITCH + col) =
                make_float2(acc[mt][bt][0], acc[mt][bt][1]);
            *reinterpret_cast<float2*>(fr + (row + 8) * FR_PITCH + col) =
                make_float2(acc[mt][bt][2], acc[mt][bt][3]);
        }
    }
    __syncthreads();

    float* yb = y + (size_t)b * TOUT;
    const int k = tid;
    if (k == 0) {
        #pragma unroll
        for (int j = 0; j < 32; ++j)
            atomicAdd(&yb[(size_t)32 * k0 + j], fr[j]);
    } else {
        const float* f0 = fr + k * FR_PITCH;
        const float* f1 = fr + (k - 1) * FR_PITCH + 32;
        float4* o = reinterpret_cast<float4*>(yb + (size_t)32 * (k0 + k));
        #pragma unroll
        for (int q = 0; q < 8; ++q)
            o[q] = make_float4(f0[4*q+0] + f1[4*q+0], f0[4*q+1] + f1[4*q+1],
                               f0[4*q+2] + f1[4*q+2], f0[4*q+3] + f1[4*q+3]);
    }
    if (k == 127) {
        const float* f1 = fr + 127 * FR_PITCH + 32;
        #pragma unroll
        for (int j = 0; j < 32; ++j)
            atomicAdd(&yb[(size_t)32 * (k0 + KTILE) + j], f1[j]);
    }
}

extern "C" void kernel_launch(void* const* d_in, const int* in_sizes, int n_in,
                              void* d_out, int out_size) {
    const float* c = (const float*)d_in[0];
    const float* V = (const float*)d_in[1];
    if (in_sizes[0] == L_DIM * N_DIM) { c = (const float*)d_in[1]; V = (const float*)d_in[0]; }
    float* y = (float*)d_out;

    static int smem_set = 0;
    if (!smem_set) {
        cudaFuncSetAttribute(decoder_kernel,
                             cudaFuncAttributeMaxDynamicSharedMemorySize, SMEM_BYTES);
        smem_set = 1;
    }

    const int prep_threads = 16384 + 8 * 257 * 32;
    prep_kernel<<<(prep_threads + 255) / 256, 256>>>(V, y);

    dim3 grid(K_DIM / KTILE, 8);
    decoder_kernel<<<grid, 128, SMEM_BYTES>>>(c, y);
}

// round 6
// speedup vs baseline: 1.3451x; 1.3451x over previous
#include <cuda_runtime.h>
#include <cstdint>

#define N_DIM   512
#define K_DIM   32768
#define L_DIM   64
#define KTILE   128
#define TOUT    1048608
#define FR_PITCH 66

// V pre-formatted as tf32 B-fragments: [ss(64)][bt(8)][lane(32)] float2
__device__ float2 g_vf[64 * 8 * 32];

static __device__ __forceinline__ uint32_t f2tf32(float f) {
    uint32_t u;
    asm("cvt.rna.tf32.f32 %0, %1;" : "=r"(u) : "f"(f));
    return u;
}
static __device__ __forceinline__ void mma_tf32(float d[4], const uint32_t a[4],
                                                const uint32_t b[2]) {
    asm volatile(
        "mma.sync.aligned.m16n8k8.row.col.f32.tf32.tf32.f32 "
        "{%0,%1,%2,%3}, {%4,%5,%6,%7}, {%8,%9}, {%0,%1,%2,%3};"
        : "+f"(d[0]), "+f"(d[1]), "+f"(d[2]), "+f"(d[3])
        : "r"(a[0]), "r"(a[1]), "r"(a[2]), "r"(a[3]), "r"(b[0]), "r"(b[1]));
}

// ---- fused prep: V -> tf32 B-fragments, zero boundary tiles ----
__global__ void prep_kernel(const float* __restrict__ V, float* __restrict__ y) {
    const int idx = blockIdx.x * blockDim.x + threadIdx.x;
    if (idx < 16384) {
        const int lane = idx & 31;
        const int bt   = (idx >> 5) & 7;
        const int ss   = idx >> 8;                 // 0..63
        const int grp  = lane >> 2, qid = lane & 3;
        const int l = bt * 8 + grp;
        const int n = ss * 8 + qid;
        float2 v;
        v.x = __uint_as_float(f2tf32(V[l * N_DIM + n]));
        v.y = __uint_as_float(f2tf32(V[l * N_DIM + n + 4]));
        g_vf[idx] = v;
    } else {
        const int i = idx - 16384;
        if (i < 8 * 257 * 32) {
            const int b = i / (257 * 32);
            const int r = i % (257 * 32);
            const int t = r >> 5, j = r & 31;
            y[(size_t)b * TOUT + (size_t)t * 4096 + j] = 0.f;
        }
    }
}

// 8 raw A loads for one ss-step: rows n = 8ss+qid (+4), m offsets {0,8,16,24}
static __device__ __forceinline__ void load_a(uint32_t r[8], const float* p0) {
    const float* p1 = p0 + 4 * (size_t)K_DIM;
    r[0] = __float_as_uint(__ldg(p0));
    r[1] = __float_as_uint(__ldg(p0 + 8));
    r[2] = __float_as_uint(__ldg(p0 + 16));
    r[3] = __float_as_uint(__ldg(p0 + 24));
    r[4] = __float_as_uint(__ldg(p1));
    r[5] = __float_as_uint(__ldg(p1 + 8));
    r[6] = __float_as_uint(__ldg(p1 + 16));
    r[7] = __float_as_uint(__ldg(p1 + 24));
}

// ---- main: CTA = (b, 128 frames), 4 free-running warps, no main-loop syncs ----
__global__ void __launch_bounds__(128, 4)
decoder_kernel(const float* __restrict__ c, float* __restrict__ y) {
    __shared__ __align__(16) float fr[KTILE * FR_PITCH];   // epilogue only

    const int tid  = threadIdx.x;
    const int wid  = tid >> 5;
    const int lane = tid & 31;
    const int grp  = lane >> 2;
    const int qid  = lane & 3;
    const int k0   = blockIdx.x * KTILE;
    const int b    = blockIdx.y;
    const int wm   = wid * 32;

    // warp+lane base: c[b, n, k0 + wm + grp], n advances by 8 per ss (row qid)
    const float* ab = c + ((size_t)b * N_DIM) * K_DIM + (size_t)(k0 + wm + grp);

    float acc[2][8][4];
    #pragma unroll
    for (int mt = 0; mt < 2; ++mt)
        #pragma unroll
        for (int bt = 0; bt < 8; ++bt)
            #pragma unroll
            for (int r = 0; r < 4; ++r) acc[mt][bt][r] = 0.f;

    uint32_t nraw[8];
    load_a(nraw, ab + (size_t)qid * K_DIM);      // ss = 0

    #pragma unroll 2
    for (int ss = 0; ss < 64; ++ss) {
        uint32_t araw[8];
        #pragma unroll
        for (int i = 0; i < 8; ++i) araw[i] = nraw[i];

        // prefetch next ss (clamped; redundant final load hits L2)
        const int ssn = (ss + 1 < 64) ? ss + 1 : 63;
        load_a(nraw, ab + (size_t)(8 * ssn + qid) * K_DIM);

        // B fragments (L1-hot, coalesced)
        const float2* vf = g_vf + ss * 256 + lane;
        uint32_t bf[8][2];
        #pragma unroll
        for (int bt = 0; bt < 8; ++bt) {
            float2 bv = __ldg(vf + bt * 32);
            bf[bt][0] = __float_as_uint(bv.x);
            bf[bt][1] = __float_as_uint(bv.y);
        }

        uint32_t a[2][4];
        #pragma unroll
        for (int mt = 0; mt < 2; ++mt) {
            a[mt][0] = f2tf32(__uint_as_float(araw[2 * mt]));
            a[mt][1] = f2tf32(__uint_as_float(araw[2 * mt + 1]));
            a[mt][2] = f2tf32(__uint_as_float(araw[4 + 2 * mt]));
            a[mt][3] = f2tf32(__uint_as_float(araw[4 + 2 * mt + 1]));
        }

        #pragma unroll
        for (int bt = 0; bt < 8; ++bt) {
            mma_tf32(acc[0][bt], a[0], bf[bt]);
            mma_tf32(acc[1][bt], a[1], bf[bt]);
        }
    }

    // ---- epilogue: stage frames, overlap-add ----
    #pragma unroll
    for (int mt = 0; mt < 2; ++mt) {
        #pragma unroll
        for (int bt = 0; bt < 8; ++bt) {
            const int row = wm + mt * 16 + grp;
            const int col = bt * 8 + 2 * qid;
            *reinterpret_cast<float2*>(fr + row * FR_PITCH + col) =
                make_float2(acc[mt][bt][0], acc[mt][bt][1]);
            *reinterpret_cast<float2*>(fr + (row + 8) * FR_PITCH + col) =
                make_float2(acc[mt][bt][2], acc[mt][bt][3]);
        }
    }
    __syncthreads();

    float* yb = y + (size_t)b * TOUT;
    const int k = tid;   // 128 threads = 128 frames
    if (k == 0) {
        #pragma unroll
        for (int j = 0; j < 32; ++j)
            atomicAdd(&yb[(size_t)32 * k0 + j], fr[j]);
    } else {
        const float* f0 = fr + k * FR_PITCH;
        const float* f1 = fr + (k - 1) * FR_PITCH + 32;
        float4* o = reinterpret_cast<float4*>(yb + (size_t)32 * (k0 + k));
        #pragma unroll
        for (int q = 0; q < 8; ++q)
            o[q] = make_float4(f0[4*q+0] + f1[4*q+0], f0[4*q+1] + f1[4*q+1],
                               f0[4*q+2] + f1[4*q+2], f0[4*q+3] + f1[4*q+3]);
    }
    if (k == 127) {
        const float* f1 = fr + 127 * FR_PITCH + 32;
        #pragma unroll
        for (int j = 0; j < 32; ++j)
            atomicAdd(&yb[(size_t)32 * (k0 + KTILE) + j], f1[j]);
    }
}

extern "C" void kernel_launch(void* const* d_in, const int* in_sizes, int n_in,
                              void* d_out, int out_size) {
    const float* c = (const float*)d_in[0];
    const float* V = (const float*)d_in[1];
    if (in_sizes[0] == L_DIM * N_DIM) { c = (const float*)d_in[1]; V = (const float*)d_in[0]; }
    float* y = (float*)d_out;

    const int prep_threads = 16384 + 8 * 257 * 32;
    prep_kernel<<<(prep_threads + 255) / 256, 256>>>(V, y);

    dim3 grid(K_DIM / KTILE, 8);   // (256, 8)
    decoder_kernel<<<grid, 128>>>(c, y);
}

// round 7
// speedup vs baseline: 1.9011x; 1.4133x over previous
#include <cuda_runtime.h>
#include <cstdint>

#define N_DIM   512
#define K_DIM   32768
#define L_DIM   64
#define KTILE   128
#define TOUT    1048608
#define FR_PITCH 66

#define WPITCH  40                       // floats per staged row (bank = 8*qid+grp)
#define STG_FL  (8 * WPITCH)             // 320 floats per stage
#define DEPTH   4
#define WARP_FL (DEPTH * STG_FL)         // 1280 floats per warp ring
#define SM_FL   8448                     // max(4*1280=5120, 128*66=8448)

// V pre-formatted as tf32 B-fragments: [ss(64)][bt(8)][lane(32)] float2
__device__ float2 g_vf[64 * 8 * 32];

static __device__ __forceinline__ uint32_t f2tf32(float f) {
    uint32_t u;
    asm("cvt.rna.tf32.f32 %0, %1;" : "=r"(u) : "f"(f));
    return u;
}
static __device__ __forceinline__ uint32_t smem_u32(const void* p) {
    uint32_t a;
    asm("{ .reg .u64 t; cvta.to.shared.u64 t, %1; cvt.u32.u64 %0, t; }" : "=r"(a) : "l"(p));
    return a;
}
static __device__ __forceinline__ void cp_async16(uint32_t dst, const void* src) {
    asm volatile("cp.async.cg.shared.global [%0], [%1], 16;" :: "r"(dst), "l"(src));
}
static __device__ __forceinline__ void cp_commit() {
    asm volatile("cp.async.commit_group;" ::: "memory");
}
template <int N> static __device__ __forceinline__ void cp_wait() {
    asm volatile("cp.async.wait_group %0;" :: "n"(N) : "memory");
}
static __device__ __forceinline__ void mma_tf32(float d[4], const uint32_t a[4],
                                                const uint32_t b[2]) {
    asm volatile(
        "mma.sync.aligned.m16n8k8.row.col.f32.tf32.tf32.f32 "
        "{%0,%1,%2,%3}, {%4,%5,%6,%7}, {%8,%9}, {%0,%1,%2,%3};"
        : "+f"(d[0]), "+f"(d[1]), "+f"(d[2]), "+f"(d[3])
        : "r"(a[0]), "r"(a[1]), "r"(a[2]), "r"(a[3]), "r"(b[0]), "r"(b[1]));
}

// ---- fused prep: V -> tf32 B-fragments, zero boundary tiles ----
__global__ void prep_kernel(const float* __restrict__ V, float* __restrict__ y) {
    const int idx = blockIdx.x * blockDim.x + threadIdx.x;
    if (idx < 16384) {
        const int lane = idx & 31;
        const int bt   = (idx >> 5) & 7;
        const int ss   = idx >> 8;
        const int grp  = lane >> 2, qid = lane & 3;
        const int l = bt * 8 + grp;
        const int n = ss * 8 + qid;
        float2 v;
        v.x = __uint_as_float(f2tf32(V[l * N_DIM + n]));
        v.y = __uint_as_float(f2tf32(V[l * N_DIM + n + 4]));
        g_vf[idx] = v;
    } else {
        const int i = idx - 16384;
        if (i < 8 * 257 * 32) {
            const int b = i / (257 * 32);
            const int r = i % (257 * 32);
            const int t = r >> 5, j = r & 31;
            y[(size_t)b * TOUT + (size_t)t * 4096 + j] = 0.f;
        }
    }
}

// ---- main: CTA = (b, 128 frames), 4 free-running warps, per-warp cp.async ring ----
__global__ void __launch_bounds__(128, 4)
decoder_kernel(const float* __restrict__ c, float* __restrict__ y) {
    __shared__ __align__(16) float sm[SM_FL];

    const int tid  = threadIdx.x;
    const int wid  = tid >> 5;
    const int lane = tid & 31;
    const int grp  = lane >> 2;
    const int qid  = lane & 3;
    const int k0   = blockIdx.x * KTILE;
    const int b    = blockIdx.y;
    const int wm   = wid * 32;

    // warp-private gmem base: c[b, n, k0 + wm + ...]
    const float* cw = c + ((size_t)b * N_DIM) * K_DIM + (size_t)(k0 + wm);
    float* ring = sm + wid * WARP_FL;
    const uint32_t ring_a = smem_u32(ring);

    // cp.async lane mapping: rows r0, r0+4 ; 16B segment seg
    const int r0  = lane >> 3;          // 0..3
    const int seg = lane & 7;           // 0..7

    float acc[2][8][4];
    #pragma unroll
    for (int mt = 0; mt < 2; ++mt)
        #pragma unroll
        for (int bt = 0; bt < 8; ++bt)
            #pragma unroll
            for (int r = 0; r < 4; ++r) acc[mt][bt][r] = 0.f;

    // prologue: stages 0..2
    #pragma unroll
    for (int ps = 0; ps < DEPTH - 1; ++ps) {
        const uint32_t dst = ring_a + (uint32_t)(ps * STG_FL * 4);
        #pragma unroll
        for (int j = 0; j < 2; ++j) {
            const int row = r0 + 4 * j;
            cp_async16(dst + (uint32_t)((row * WPITCH + seg * 4) * 4),
                       cw + (size_t)(8 * ps + row) * K_DIM + seg * 4);
        }
        cp_commit();
    }

    #pragma unroll 2
    for (int ss = 0; ss < 64; ++ss) {
        cp_wait<DEPTH - 2>();           // stage ss resident
        __syncwarp();

        // issue stage ss+3 into its ring slot (consumed at ss-1)
        if (ss + DEPTH - 1 < 64) {
            const int ts = ss + DEPTH - 1;
            const uint32_t dst = ring_a + (uint32_t)((ts & (DEPTH - 1)) * STG_FL * 4);
            #pragma unroll
            for (int j = 0; j < 2; ++j) {
                const int row = r0 + 4 * j;
                cp_async16(dst + (uint32_t)((row * WPITCH + seg * 4) * 4),
                           cw + (size_t)(8 * ts + row) * K_DIM + seg * 4);
            }
        }
        cp_commit();                    // always commit (empty groups at tail)

        // B fragments (L1-hot)
        const float2* vf = g_vf + ss * 256 + lane;
        uint32_t bf[8][2];
        #pragma unroll
        for (int bt = 0; bt < 8; ++bt) {
            float2 bv = __ldg(vf + bt * 32);
            bf[bt][0] = __float_as_uint(bv.x);
            bf[bt][1] = __float_as_uint(bv.y);
        }

        // A fragments from warp-private SMEM (conflict-free: bank = 8*qid+grp)
        const float* cs = ring + (ss & (DEPTH - 1)) * STG_FL;
        const float* ar0 = cs + qid * WPITCH + grp;
        const float* ar1 = cs + (qid + 4) * WPITCH + grp;
        uint32_t a[2][4];
        #pragma unroll
        for (int mt = 0; mt < 2; ++mt) {
            a[mt][0] = f2tf32(ar0[16 * mt]);
            a[mt][1] = f2tf32(ar0[16 * mt + 8]);
            a[mt][2] = f2tf32(ar1[16 * mt]);
            a[mt][3] = f2tf32(ar1[16 * mt + 8]);
        }

        #pragma unroll
        for (int bt = 0; bt < 8; ++bt) {
            mma_tf32(acc[0][bt], a[0], bf[bt]);
            mma_tf32(acc[1][bt], a[1], bf[bt]);
        }
    }

    __syncthreads();   // rings dead; safe to reuse sm as frame buffer

    // ---- epilogue: stage frames, overlap-add ----
    float* fr = sm;
    #pragma unroll
    for (int mt = 0; mt < 2; ++mt) {
        #pragma unroll
        for (int bt = 0; bt < 8; ++bt) {
            const int row = wm + mt * 16 + grp;
            const int col = bt * 8 + 2 * qid;
            *reinterpret_cast<float2*>(fr + row * FR_PITCH + col) =
                make_float2(acc[mt][bt][0], acc[mt][bt][1]);
            *reinterpret_cast<float2*>(fr + (row + 8) * FR_PITCH + col) =
                make_float2(acc[mt][bt][2], acc[mt][bt][3]);
        }
    }
    __syncthreads();

    float* yb = y + (size_t)b * TOUT;
    const int k = tid;
    if (k == 0) {
        #pragma unroll
        for (int j = 0; j < 32; ++j)
            atomicAdd(&yb[(size_t)32 * k0 + j], fr[j]);
    } else {
        const float* f0 = fr + k * FR_PITCH;
        const float* f1 = fr + (k - 1) * FR_PITCH + 32;
        float4* o = reinterpret_cast<float4*>(yb + (size_t)32 * (k0 + k));
        #pragma unroll
        for (int q = 0; q < 8; ++q)
            o[q] = make_float4(f0[4*q+0] + f1[4*q+0], f0[4*q+1] + f1[4*q+1],
                               f0[4*q+2] + f1[4*q+2], f0[4*q+3] + f1[4*q+3]);
    }
    if (k == 127) {
        const float* f1 = fr + 127 * FR_PITCH + 32;
        #pragma unroll
        for (int j = 0; j < 32; ++j)
            atomicAdd(&yb[(size_t)32 * (k0 + KTILE) + j], f1[j]);
    }
}

extern "C" void kernel_launch(void* const* d_in, const int* in_sizes, int n_in,
                              void* d_out, int out_size) {
    const float* c = (const float*)d_in[0];
    const float* V = (const float*)d_in[1];
    if (in_sizes[0] == L_DIM * N_DIM) { c = (const float*)d_in[1]; V = (const float*)d_in[0]; }
    float* y = (float*)d_out;

    const int prep_threads = 16384 + 8 * 257 * 32;
    prep_kernel<<<(prep_threads + 255) / 256, 256>>>(V, y);

    dim3 grid(K_DIM / KTILE, 8);
    decoder_kernel<<<grid, 128>>>(c, y);
}